// round 15
// baseline (speedup 1.0000x reference)
#include <cuda_runtime.h>
#include <math.h>

// ---------------------------------------------------------------------------
// Scratch. N = 1,000,000 fits in 1<<20.
// ---------------------------------------------------------------------------
#define MAXN (1 << 20)
__device__ float4        g_aggd[MAXN];        // pass1: (sum_x, sum_y, degree, 0)
__device__ float2        g_xn[MAXN];          // node state (pass-1 input only)
__device__ float2        g_agg[MAXN];         // pass2 float fallback accumulator
__device__ unsigned int  g_cntA[MAXN];        // pass2: count of class-0 sources
__device__ unsigned int  g_cntB[MAXN];        // pass2: count of class-2 sources
__device__ unsigned char g_clsp[MAXN / 4];    // 2-bit class per node, packed 4/byte
__device__ int           g_idx64;             // 1 if edge_index is int64
__device__ int           g_notclean;          // 1 if any node is class 3 (general)
__device__ int           g_anyAB;             // 1 if any node is class 0 or 2

#define EPSF 1e-15f

#define PDL_WAIT()    asm volatile("griddepcontrol.wait;" ::: "memory")
#define PDL_TRIGGER() asm volatile("griddepcontrol.launch_dependents;" ::: "memory")

__device__ __forceinline__ void red_add_f32x4(float4* p, float a, float b,
                                              float c, float d) {
    asm volatile("red.global.add.v4.f32 [%0], {%1, %2, %3, %4};"
                 :: "l"(p), "f"(a), "f"(b), "f"(c), "f"(d)
                 : "memory");
}
__device__ __forceinline__ void red_add_f32x2(float2* p, float vx, float vy) {
    asm volatile("red.global.add.v2.f32 [%0], {%1, %2};"
                 :: "l"(p), "f"(vx), "f"(vy)
                 : "memory");
}
__device__ __forceinline__ void red_add_u32(unsigned int* p, unsigned int v) {
    asm volatile("red.global.add.u32 [%0], %1;"
                 :: "l"(p), "r"(v)
                 : "memory");
}
__device__ __forceinline__ float2 ldcg_f2(const float2* p) {
    float2 r;
    asm volatile("ld.global.cg.v2.f32 {%0, %1}, [%2];"
                 : "=f"(r.x), "=f"(r.y) : "l"(p));
    return r;
}
__device__ __forceinline__ float4 ldcg_f4(const float4* p) {
    float4 r;
    asm volatile("ld.global.cg.v4.f32 {%0, %1, %2, %3}, [%4];"
                 : "=f"(r.x), "=f"(r.y), "=f"(r.z), "=f"(r.w) : "l"(p));
    return r;
}

// Shared classification: from raw pass-1 sums (a0,a1) compute class + new x.
__device__ __forceinline__ unsigned int classify(float a0, float a1,
                                                 float w00, float w01,
                                                 float w10, float w11,
                                                 float& x0, float& x1) {
    float y0 = fmaf(a1, w10, a0 * w00);
    float y1 = fmaf(a1, w11, a0 * w01);
    float r0 = fmaxf(y0, 0.0f);
    float r1 = fmaxf(y1, 0.0f);
    if (r0 == 0.0f && r1 > 1e-6f) { x0 = 0.0f; x1 = 1.0f; return 1u; }
    if (r1 == 0.0f && r0 > 1e-6f) { x0 = 1.0f; x1 = 0.0f; return 0u; }
    if (r0 == 0.0f && r1 == 0.0f) { x0 = 0.0f; x1 = 0.0f; return 2u; }
    float inv = 1.0f / (sqrtf(r0 * r0 + r1 * r1) + EPSF);
    x0 = r0 * inv; x1 = r1 * inv;
    return 3u;
}

// ---------------------------------------------------------------------------
// Kernel 1: normalize x into g_xn (2 nodes/thread), zero g_aggd, zero the
// pass-2 accumulators (g_agg + cnt arrays — safe this early, nothing touches
// them until pass 2; the extra stores hide under scatter1's PDL ramp),
// detect index dtype.
// ---------------------------------------------------------------------------
__global__ void k_init(const float4* __restrict__ x, int Npairs, int N,
                       const long long* __restrict__ ei, long long n_words) {
    PDL_TRIGGER();
    int i = blockIdx.x * blockDim.x + threadIdx.x;
    if (i < Npairs) {
        float4 v = x[i];
        float inv0 = 1.0f / (sqrtf(v.x * v.x + v.y * v.y) + EPSF);
        float inv1 = 1.0f / (sqrtf(v.z * v.z + v.w * v.w) + EPSF);
        ((float4*)g_xn)[i] = make_float4(v.x * inv0, v.y * inv0,
                                         v.z * inv1, v.w * inv1);
        g_aggd[2 * i]     = make_float4(0.f, 0.f, 0.f, 0.f);
        g_aggd[2 * i + 1] = make_float4(0.f, 0.f, 0.f, 0.f);
        ((float4*)g_agg)[i] = make_float4(0.f, 0.f, 0.f, 0.f);
        ((uint2*)g_cntA)[i] = make_uint2(0u, 0u);
        ((uint2*)g_cntB)[i] = make_uint2(0u, 0u);
    }
    if (blockIdx.x == 0) {
        if (threadIdx.x == 0) { g_notclean = 0; g_anyAB = 0; }
        __shared__ int bad;
        if (threadIdx.x == 0) bad = 0;
        __syncthreads();
        long long lim = n_words < 2048 ? n_words : 2048;
        int local_bad = 0;
        for (long long w = threadIdx.x; w < lim; w += blockDim.x) {
            long long v = ei[w];
            if (v < 0 || v >= (long long)N) local_bad = 1;
        }
        if (local_bad) bad = 1;
        __syncthreads();
        if (threadIdx.x == 0) g_idx64 = bad ? 0 : 1;
    }
}

// ---------------------------------------------------------------------------
// Kernel 2: pass-1 scatter with fused degree count:
// g_aggd[dst] += (xn[src].x, xn[src].y, 1, 0) via one v4 red per edge.
// Measured-best shape: one quad per thread, __ldcs index loads, L2 gathers.
// ---------------------------------------------------------------------------
__global__ void __launch_bounds__(256) k_scatter(const void* __restrict__ eiv, long long E) {
    PDL_TRIGGER();
    long long q = (long long)blockIdx.x * blockDim.x + threadIdx.x;
    long long quads = E >> 2;

    int4 s = make_int4(0, 0, 0, 0), d = make_int4(0, 0, 0, 0);
    if (q < quads) {
        const int* src32 = (const int*)eiv;
        s = __ldcs((const int4*)(src32 + 4 * q));
        d = __ldcs((const int4*)(src32 + E + 4 * q));
    }

    PDL_WAIT();

    if (g_idx64 == 0) {
        const int* src = (const int*)eiv;
        const int* dst = src + E;
        if (q < quads) {
            float2 v0 = ldcg_f2(&g_xn[s.x]);
            float2 v1 = ldcg_f2(&g_xn[s.y]);
            float2 v2 = ldcg_f2(&g_xn[s.z]);
            float2 v3 = ldcg_f2(&g_xn[s.w]);
            red_add_f32x4(&g_aggd[d.x], v0.x, v0.y, 1.0f, 0.0f);
            red_add_f32x4(&g_aggd[d.y], v1.x, v1.y, 1.0f, 0.0f);
            red_add_f32x4(&g_aggd[d.z], v2.x, v2.y, 1.0f, 0.0f);
            red_add_f32x4(&g_aggd[d.w], v3.x, v3.y, 1.0f, 0.0f);
        }
        if (q == 0) {
            for (long long e = quads * 4; e < E; e++) {
                float2 v = ldcg_f2(&g_xn[src[e]]);
                red_add_f32x4(&g_aggd[dst[e]], v.x, v.y, 1.0f, 0.0f);
            }
        }
    } else {
        const long long* src = (const long long*)eiv;
        const long long* dst = src + E;
        if (q < quads) {
            longlong2 s0 = __ldcs((const longlong2*)(src + 4 * q));
            longlong2 s1 = __ldcs((const longlong2*)(src + 4 * q) + 1);
            longlong2 d0 = __ldcs((const longlong2*)(dst + 4 * q));
            longlong2 d1 = __ldcs((const longlong2*)(dst + 4 * q) + 1);
            float2 v0 = ldcg_f2(&g_xn[(int)s0.x]);
            float2 v1 = ldcg_f2(&g_xn[(int)s0.y]);
            float2 v2 = ldcg_f2(&g_xn[(int)s1.x]);
            float2 v3 = ldcg_f2(&g_xn[(int)s1.y]);
            red_add_f32x4(&g_aggd[(int)d0.x], v0.x, v0.y, 1.0f, 0.0f);
            red_add_f32x4(&g_aggd[(int)d0.y], v1.x, v1.y, 1.0f, 0.0f);
            red_add_f32x4(&g_aggd[(int)d1.x], v2.x, v2.y, 1.0f, 0.0f);
            red_add_f32x4(&g_aggd[(int)d1.y], v3.x, v3.y, 1.0f, 0.0f);
        }
        if (q == 0) {
            for (long long e = quads * 4; e < E; e++) {
                float2 v = ldcg_f2(&g_xn[(int)src[e]]);
                red_add_f32x4(&g_aggd[(int)dst[e]], v.x, v.y, 1.0f, 0.0f);
            }
        }
    }
}

// ---------------------------------------------------------------------------
// Kernel 3: CLASSIFY-ONLY. Read g_aggd (16MB), write packed classes (256KB)
// + flags. No other state to prepare: accumulators were zeroed in k_init and
// the class-3 fallback reconstructs xn inline from g_aggd.
// ---------------------------------------------------------------------------
__global__ void k_mid(const float* __restrict__ W, int Nquads) {
    PDL_TRIGGER();
    int i = blockIdx.x * blockDim.x + threadIdx.x;
    float w00 = W[0], w01 = W[1], w10 = W[2], w11 = W[3];
    PDL_WAIT();
    if (i >= Nquads) return;

    unsigned int clsbyte = 0;
    bool dirty = false, anyab = false;

    #pragma unroll
    for (int j = 0; j < 4; j++) {
        float4 ad = g_aggd[4 * i + j];
        float x0, x1;
        unsigned int c = classify(ad.x, ad.y, w00, w01, w10, w11, x0, x1);
        clsbyte |= c << (2 * j);
        if (c == 3u) dirty = true;
        else if (c != 1u) anyab = true;
    }

    g_clsp[i] = (unsigned char)clsbyte;
    if (dirty) g_notclean = 1;
    if (anyab) g_anyAB = 1;
}

// ---------------------------------------------------------------------------
// Kernel 2b: pass-2 scatter, tiered, grid-stride small grid (512 blocks).
// Expected case: read flags, exit (~fixed launch floor). Rare clean: count
// rare-class sources via the L1-resident packed class array. Class-3
// present: gather g_aggd[src] (16B, one sector) and classify inline to
// reconstruct xn — no g_xn rebuild needed.
// ---------------------------------------------------------------------------
__device__ __forceinline__ unsigned int cls_of(int node) {
    unsigned int b = (unsigned int)g_clsp[node >> 2];
    return (b >> ((node & 3) << 1)) & 3u;
}
__device__ __forceinline__ void count_rare(unsigned int c, int dnode) {
    if (c == 0u)      red_add_u32(&g_cntA[dnode], 1u);
    else if (c == 2u) red_add_u32(&g_cntB[dnode], 1u);
}

__global__ void __launch_bounds__(256) k_scatter2(const void* __restrict__ eiv,
                                                  long long E,
                                                  const float* __restrict__ W) {
    PDL_TRIGGER();
    PDL_WAIT();
    if (g_notclean == 0 && g_anyAB == 0) return;   // degree-only: nothing to do

    long long tid    = (long long)blockIdx.x * blockDim.x + threadIdx.x;
    long long stride = (long long)gridDim.x * blockDim.x;
    long long quads  = E >> 2;

    if (g_notclean == 0) {
        if (g_idx64 == 0) {
            const int* src = (const int*)eiv;
            const int* dst = src + E;
            for (long long q = tid; q < quads; q += stride) {
                int4 s = __ldcs((const int4*)(src + 4 * q));
                int4 d = __ldcs((const int4*)(dst + 4 * q));
                count_rare(cls_of(s.x), d.x);
                count_rare(cls_of(s.y), d.y);
                count_rare(cls_of(s.z), d.z);
                count_rare(cls_of(s.w), d.w);
            }
            if (tid == 0) {
                for (long long e = quads * 4; e < E; e++)
                    count_rare(cls_of(src[e]), dst[e]);
            }
        } else {
            const long long* src = (const long long*)eiv;
            const long long* dst = src + E;
            for (long long q = tid; q < quads; q += stride) {
                longlong2 s0 = __ldcs((const longlong2*)(src + 4 * q));
                longlong2 s1 = __ldcs((const longlong2*)(src + 4 * q) + 1);
                longlong2 d0 = __ldcs((const longlong2*)(dst + 4 * q));
                longlong2 d1 = __ldcs((const longlong2*)(dst + 4 * q) + 1);
                count_rare(cls_of((int)s0.x), (int)d0.x);
                count_rare(cls_of((int)s0.y), (int)d0.y);
                count_rare(cls_of((int)s1.x), (int)d1.x);
                count_rare(cls_of((int)s1.y), (int)d1.y);
            }
            if (tid == 0) {
                for (long long e = quads * 4; e < E; e++)
                    count_rare(cls_of((int)src[e]), (int)dst[e]);
            }
        }
    } else {
        // Full float fallback: classify src from g_aggd inline.
        float w00 = W[0], w01 = W[1], w10 = W[2], w11 = W[3];
        if (g_idx64 == 0) {
            const int* src = (const int*)eiv;
            const int* dst = src + E;
            for (long long q = tid; q < quads; q += stride) {
                int4 s = __ldcs((const int4*)(src + 4 * q));
                int4 d = __ldcs((const int4*)(dst + 4 * q));
                #pragma unroll
                for (int j = 0; j < 4; j++) {
                    int sn = (&s.x)[j], dn = (&d.x)[j];
                    float4 ad = ldcg_f4(&g_aggd[sn]);
                    float x0, x1;
                    classify(ad.x, ad.y, w00, w01, w10, w11, x0, x1);
                    red_add_f32x2(&g_agg[dn], x0, x1);
                }
            }
            if (tid == 0) {
                for (long long e = quads * 4; e < E; e++) {
                    float4 ad = ldcg_f4(&g_aggd[src[e]]);
                    float x0, x1;
                    classify(ad.x, ad.y, w00, w01, w10, w11, x0, x1);
                    red_add_f32x2(&g_agg[dst[e]], x0, x1);
                }
            }
        } else {
            const long long* src = (const long long*)eiv;
            const long long* dst = src + E;
            for (long long q = tid; q < quads; q += stride) {
                #pragma unroll
                for (int j = 0; j < 4; j++) {
                    int sn = (int)src[4 * q + j], dn = (int)dst[4 * q + j];
                    float4 ad = ldcg_f4(&g_aggd[sn]);
                    float x0, x1;
                    classify(ad.x, ad.y, w00, w01, w10, w11, x0, x1);
                    red_add_f32x2(&g_agg[dn], x0, x1);
                }
            }
            if (tid == 0) {
                for (long long e = quads * 4; e < E; e++) {
                    float4 ad = ldcg_f4(&g_aggd[(int)src[e]]);
                    float x0, x1;
                    classify(ad.x, ad.y, w00, w01, w10, w11, x0, x1);
                    red_add_f32x2(&g_agg[(int)dst[e]], x0, x1);
                }
            }
        }
    }
}

// ---------------------------------------------------------------------------
// Kernel 4: final. Three tiers:
//   all-class-1 (expected): agg = (0, deg)        (reads only g_aggd)
//   clean w/ rare classes:  agg = (cntA, deg - cntA - cnt2)
//   class-3 present:        float g_agg fallback
// ---------------------------------------------------------------------------
__global__ void k_final(const float* __restrict__ W,
                        const float* __restrict__ fw,
                        float2* __restrict__ out, int Npairs) {
    int i = blockIdx.x * blockDim.x + threadIdx.x;
    float w00 = W[0], w01 = W[1], w10 = W[2], w11 = W[3];
    float f0 = fw[0], f1 = fw[1];
    PDL_WAIT();
    if (i >= Npairs) return;

    float4 a;
    if (g_notclean == 0) {
        float deg0 = g_aggd[2 * i].z;
        float deg1 = g_aggd[2 * i + 1].z;
        if (g_anyAB == 0) {
            a = make_float4(0.0f, deg0, 0.0f, deg1);
        } else {
            uint2 cA = ((const uint2*)g_cntA)[i];
            uint2 c2 = ((const uint2*)g_cntB)[i];
            float a0 = (float)cA.x;
            float a2 = (float)cA.y;
            a = make_float4(a0, deg0 - a0 - (float)c2.x,
                            a2, deg1 - a2 - (float)c2.y);
        }
    } else {
        a = ((const float4*)g_agg)[i];
    }
    float y0 = fmaxf(fmaf(a.y, w10, a.x * w00), 0.0f);
    float y1 = fmaxf(fmaf(a.y, w11, a.x * w01), 0.0f);
    float y2 = fmaxf(fmaf(a.w, w10, a.z * w00), 0.0f);
    float y3 = fmaxf(fmaf(a.w, w11, a.z * w01), 0.0f);
    float s0 = fmaf(y1, f1, y0 * f0);
    float s1 = fmaf(y3, f1, y2 * f0);
    out[i] = make_float2(1.0f / (1.0f + expf(-s0)),
                         1.0f / (1.0f + expf(-s1)));
}

// ---------------------------------------------------------------------------
// Launch: init -> scatter(v4+deg) -> mid(classify) -> scatter2(gated) ->
// final, all under PDL. Graph-capturable, allocation-free.
// ---------------------------------------------------------------------------
extern "C" void kernel_launch(void* const* d_in, const int* in_sizes, int n_in,
                              void* d_out, int out_size) {
    const float* x  = (const float*)d_in[0];
    const void*  ei = (const void*)d_in[1];
    const float* W  = (const float*)d_in[2];
    const float* fw = (const float*)d_in[3];
    float2* out = (float2*)d_out;

    int N = in_sizes[0] / 2;          // 1,000,000 (divisible by 4)
    int Npairs = N / 2;
    int Nquads = N / 4;
    long long E = (long long)in_sizes[1] / 2;
    long long equads = E >> 2;

    const int TB = 256;
    int nb_pairs = (Npairs + TB - 1) / TB;
    int nb_quads = (Nquads + TB - 1) / TB;
    int nb_scatter = (int)((equads + TB - 1) / TB);
    const int GATED_BLOCKS = 512;     // small grid: fast exit on expected path

    cudaLaunchAttribute attr[1];
    attr[0].id = cudaLaunchAttributeProgrammaticStreamSerialization;
    attr[0].val.programmaticStreamSerializationAllowed = 1;

    cudaLaunchConfig_t cfg = {};
    cfg.blockDim = dim3(TB, 1, 1);
    cfg.dynamicSmemBytes = 0;
    cfg.stream = 0;
    cfg.attrs = attr;
    cfg.numAttrs = 1;

    cfg.gridDim = dim3(nb_pairs, 1, 1);
    cudaLaunchKernelEx(&cfg, k_init, (const float4*)x, Npairs, N,
                       (const long long*)ei, E);

    cfg.gridDim = dim3(nb_scatter, 1, 1);
    cudaLaunchKernelEx(&cfg, k_scatter, (const void*)ei, E);

    cfg.gridDim = dim3(nb_quads, 1, 1);
    cudaLaunchKernelEx(&cfg, k_mid, W, Nquads);

    cfg.gridDim = dim3(GATED_BLOCKS, 1, 1);
    cudaLaunchKernelEx(&cfg, k_scatter2, (const void*)ei, E, W);

    cfg.gridDim = dim3(nb_pairs, 1, 1);
    cudaLaunchKernelEx(&cfg, k_final, W, fw, out, Npairs);

    (void)n_in; (void)out_size;
}

// round 16
// speedup vs baseline: 1.0122x; 1.0122x over previous
#include <cuda_runtime.h>
#include <math.h>

// ---------------------------------------------------------------------------
// Scratch. N = 1,000,000 fits in 1<<20.
// ---------------------------------------------------------------------------
#define MAXN (1 << 20)
__device__ float4        g_aggd[MAXN];        // pass1: (sum_x, sum_y, degree, rare-count-pack)
__device__ float2        g_xn[MAXN];          // node state (pass-1 input only)
__device__ float2        g_agg[MAXN];         // pass2 class-3 fallback accumulator
__device__ unsigned char g_clsp[MAXN / 4];    // 2-bit class per node, packed 4/byte
__device__ int           g_idx64;             // 1 if edge_index is int64
__device__ int           g_notclean;          // 1 if any node is class 3 (general)
__device__ int           g_anyAB;             // 1 if any node is class 0 or 2

#define EPSF 1e-15f
#define C2_SCALE 65536.0f   // class-2 count packed into high part of aggd.w

#define PDL_WAIT()    asm volatile("griddepcontrol.wait;" ::: "memory")
#define PDL_TRIGGER() asm volatile("griddepcontrol.launch_dependents;" ::: "memory")

__device__ __forceinline__ void red_add_f32x4(float4* p, float a, float b,
                                              float c, float d) {
    asm volatile("red.global.add.v4.f32 [%0], {%1, %2, %3, %4};"
                 :: "l"(p), "f"(a), "f"(b), "f"(c), "f"(d)
                 : "memory");
}
__device__ __forceinline__ void red_add_f32x2(float2* p, float vx, float vy) {
    asm volatile("red.global.add.v2.f32 [%0], {%1, %2};"
                 :: "l"(p), "f"(vx), "f"(vy)
                 : "memory");
}
__device__ __forceinline__ void red_add_f32(float* p, float v) {
    asm volatile("red.global.add.f32 [%0], %1;"
                 :: "l"(p), "f"(v)
                 : "memory");
}
__device__ __forceinline__ float2 ldcg_f2(const float2* p) {
    float2 r;
    asm volatile("ld.global.cg.v2.f32 {%0, %1}, [%2];"
                 : "=f"(r.x), "=f"(r.y) : "l"(p));
    return r;
}
__device__ __forceinline__ float4 ldcg_f4(const float4* p) {
    float4 r;
    asm volatile("ld.global.cg.v4.f32 {%0, %1, %2, %3}, [%4];"
                 : "=f"(r.x), "=f"(r.y), "=f"(r.z), "=f"(r.w) : "l"(p));
    return r;
}

// Shared classification: from raw pass-1 sums (a0,a1) compute class + new x.
__device__ __forceinline__ unsigned int classify(float a0, float a1,
                                                 float w00, float w01,
                                                 float w10, float w11,
                                                 float& x0, float& x1) {
    float y0 = fmaf(a1, w10, a0 * w00);
    float y1 = fmaf(a1, w11, a0 * w01);
    float r0 = fmaxf(y0, 0.0f);
    float r1 = fmaxf(y1, 0.0f);
    if (r0 == 0.0f && r1 > 1e-6f) { x0 = 0.0f; x1 = 1.0f; return 1u; }
    if (r1 == 0.0f && r0 > 1e-6f) { x0 = 1.0f; x1 = 0.0f; return 0u; }
    if (r0 == 0.0f && r1 == 0.0f) { x0 = 0.0f; x1 = 0.0f; return 2u; }
    float inv = 1.0f / (sqrtf(r0 * r0 + r1 * r1) + EPSF);
    x0 = r0 * inv; x1 = r1 * inv;
    return 3u;
}

// ---------------------------------------------------------------------------
// Kernel 1: normalize x into g_xn (2 nodes/thread), zero g_aggd + g_agg
// (g_agg is only read in the probability-zero class-3 fallback; the cnt
// arrays of earlier rounds are gone — rare counts pack into g_aggd.w).
// Detect index dtype in block 0.
// ---------------------------------------------------------------------------
__global__ void k_init(const float4* __restrict__ x, int Npairs, int N,
                       const long long* __restrict__ ei, long long n_words) {
    PDL_TRIGGER();
    int i = blockIdx.x * blockDim.x + threadIdx.x;
    if (i < Npairs) {
        float4 v = x[i];
        float inv0 = 1.0f / (sqrtf(v.x * v.x + v.y * v.y) + EPSF);
        float inv1 = 1.0f / (sqrtf(v.z * v.z + v.w * v.w) + EPSF);
        ((float4*)g_xn)[i] = make_float4(v.x * inv0, v.y * inv0,
                                         v.z * inv1, v.w * inv1);
        g_aggd[2 * i]     = make_float4(0.f, 0.f, 0.f, 0.f);
        g_aggd[2 * i + 1] = make_float4(0.f, 0.f, 0.f, 0.f);
        ((float4*)g_agg)[i] = make_float4(0.f, 0.f, 0.f, 0.f);
    }
    if (blockIdx.x == 0) {
        if (threadIdx.x == 0) { g_notclean = 0; g_anyAB = 0; }
        __shared__ int bad;
        if (threadIdx.x == 0) bad = 0;
        __syncthreads();
        long long lim = n_words < 2048 ? n_words : 2048;
        int local_bad = 0;
        for (long long w = threadIdx.x; w < lim; w += blockDim.x) {
            long long v = ei[w];
            if (v < 0 || v >= (long long)N) local_bad = 1;
        }
        if (local_bad) bad = 1;
        __syncthreads();
        if (threadIdx.x == 0) g_idx64 = bad ? 0 : 1;
    }
}

// ---------------------------------------------------------------------------
// Kernel 2: pass-1 scatter with fused degree count:
// g_aggd[dst] += (xn[src].x, xn[src].y, 1, 0) via one v4 red per edge.
// Measured-best shape: one quad per thread, __ldcs index loads, L2 gathers.
// ---------------------------------------------------------------------------
__global__ void __launch_bounds__(256) k_scatter(const void* __restrict__ eiv, long long E) {
    PDL_TRIGGER();
    long long q = (long long)blockIdx.x * blockDim.x + threadIdx.x;
    long long quads = E >> 2;

    int4 s = make_int4(0, 0, 0, 0), d = make_int4(0, 0, 0, 0);
    if (q < quads) {
        const int* src32 = (const int*)eiv;
        s = __ldcs((const int4*)(src32 + 4 * q));
        d = __ldcs((const int4*)(src32 + E + 4 * q));
    }

    PDL_WAIT();

    if (g_idx64 == 0) {
        const int* src = (const int*)eiv;
        const int* dst = src + E;
        if (q < quads) {
            float2 v0 = ldcg_f2(&g_xn[s.x]);
            float2 v1 = ldcg_f2(&g_xn[s.y]);
            float2 v2 = ldcg_f2(&g_xn[s.z]);
            float2 v3 = ldcg_f2(&g_xn[s.w]);
            red_add_f32x4(&g_aggd[d.x], v0.x, v0.y, 1.0f, 0.0f);
            red_add_f32x4(&g_aggd[d.y], v1.x, v1.y, 1.0f, 0.0f);
            red_add_f32x4(&g_aggd[d.z], v2.x, v2.y, 1.0f, 0.0f);
            red_add_f32x4(&g_aggd[d.w], v3.x, v3.y, 1.0f, 0.0f);
        }
        if (q == 0) {
            for (long long e = quads * 4; e < E; e++) {
                float2 v = ldcg_f2(&g_xn[src[e]]);
                red_add_f32x4(&g_aggd[dst[e]], v.x, v.y, 1.0f, 0.0f);
            }
        }
    } else {
        const long long* src = (const long long*)eiv;
        const long long* dst = src + E;
        if (q < quads) {
            longlong2 s0 = __ldcs((const longlong2*)(src + 4 * q));
            longlong2 s1 = __ldcs((const longlong2*)(src + 4 * q) + 1);
            longlong2 d0 = __ldcs((const longlong2*)(dst + 4 * q));
            longlong2 d1 = __ldcs((const longlong2*)(dst + 4 * q) + 1);
            float2 v0 = ldcg_f2(&g_xn[(int)s0.x]);
            float2 v1 = ldcg_f2(&g_xn[(int)s0.y]);
            float2 v2 = ldcg_f2(&g_xn[(int)s1.x]);
            float2 v3 = ldcg_f2(&g_xn[(int)s1.y]);
            red_add_f32x4(&g_aggd[(int)d0.x], v0.x, v0.y, 1.0f, 0.0f);
            red_add_f32x4(&g_aggd[(int)d0.y], v1.x, v1.y, 1.0f, 0.0f);
            red_add_f32x4(&g_aggd[(int)d1.x], v2.x, v2.y, 1.0f, 0.0f);
            red_add_f32x4(&g_aggd[(int)d1.y], v3.x, v3.y, 1.0f, 0.0f);
        }
        if (q == 0) {
            for (long long e = quads * 4; e < E; e++) {
                float2 v = ldcg_f2(&g_xn[(int)src[e]]);
                red_add_f32x4(&g_aggd[(int)dst[e]], v.x, v.y, 1.0f, 0.0f);
            }
        }
    }
}

// ---------------------------------------------------------------------------
// Kernel 3: CLASSIFY-ONLY. Read g_aggd (16MB), write packed classes (256KB)
// + flags. Nothing else to prepare.
// ---------------------------------------------------------------------------
__global__ void k_mid(const float* __restrict__ W, int Nquads) {
    PDL_TRIGGER();
    int i = blockIdx.x * blockDim.x + threadIdx.x;
    float w00 = W[0], w01 = W[1], w10 = W[2], w11 = W[3];
    PDL_WAIT();
    if (i >= Nquads) return;

    unsigned int clsbyte = 0;
    bool dirty = false, anyab = false;

    #pragma unroll
    for (int j = 0; j < 4; j++) {
        float4 ad = g_aggd[4 * i + j];
        float x0, x1;
        unsigned int c = classify(ad.x, ad.y, w00, w01, w10, w11, x0, x1);
        clsbyte |= c << (2 * j);
        if (c == 3u) dirty = true;
        else if (c != 1u) anyab = true;
    }

    g_clsp[i] = (unsigned char)clsbyte;
    if (dirty) g_notclean = 1;
    if (anyab) g_anyAB = 1;
}

// ---------------------------------------------------------------------------
// Kernel 2b: pass-2 scatter, tiered, grid-stride 512 blocks.
// Expected case: read flags, exit (~5us launch floor). Rare clean: pack
// class-0 / class-2 source counts into g_aggd[dst].w (w is zero at pass-2
// start: +1.0 per class-0, +65536.0 per class-2; exact in fp32 for counts
// up to 2^24). Class-3 present: gather g_aggd[src], classify inline, float
// red into g_agg.
// ---------------------------------------------------------------------------
__device__ __forceinline__ unsigned int cls_of(int node) {
    unsigned int b = (unsigned int)g_clsp[node >> 2];
    return (b >> ((node & 3) << 1)) & 3u;
}
__device__ __forceinline__ void count_rare(unsigned int c, int dnode) {
    if (c == 0u)      red_add_f32(&g_aggd[dnode].w, 1.0f);
    else if (c == 2u) red_add_f32(&g_aggd[dnode].w, C2_SCALE);
}

__global__ void __launch_bounds__(256) k_scatter2(const void* __restrict__ eiv,
                                                  long long E,
                                                  const float* __restrict__ W) {
    PDL_TRIGGER();
    PDL_WAIT();
    if (g_notclean == 0 && g_anyAB == 0) return;   // degree-only: nothing to do

    long long tid    = (long long)blockIdx.x * blockDim.x + threadIdx.x;
    long long stride = (long long)gridDim.x * blockDim.x;
    long long quads  = E >> 2;

    if (g_notclean == 0) {
        if (g_idx64 == 0) {
            const int* src = (const int*)eiv;
            const int* dst = src + E;
            for (long long q = tid; q < quads; q += stride) {
                int4 s = __ldcs((const int4*)(src + 4 * q));
                int4 d = __ldcs((const int4*)(dst + 4 * q));
                count_rare(cls_of(s.x), d.x);
                count_rare(cls_of(s.y), d.y);
                count_rare(cls_of(s.z), d.z);
                count_rare(cls_of(s.w), d.w);
            }
            if (tid == 0) {
                for (long long e = quads * 4; e < E; e++)
                    count_rare(cls_of(src[e]), dst[e]);
            }
        } else {
            const long long* src = (const long long*)eiv;
            const long long* dst = src + E;
            for (long long q = tid; q < quads; q += stride) {
                longlong2 s0 = __ldcs((const longlong2*)(src + 4 * q));
                longlong2 s1 = __ldcs((const longlong2*)(src + 4 * q) + 1);
                longlong2 d0 = __ldcs((const longlong2*)(dst + 4 * q));
                longlong2 d1 = __ldcs((const longlong2*)(dst + 4 * q) + 1);
                count_rare(cls_of((int)s0.x), (int)d0.x);
                count_rare(cls_of((int)s0.y), (int)d0.y);
                count_rare(cls_of((int)s1.x), (int)d1.x);
                count_rare(cls_of((int)s1.y), (int)d1.y);
            }
            if (tid == 0) {
                for (long long e = quads * 4; e < E; e++)
                    count_rare(cls_of((int)src[e]), (int)dst[e]);
            }
        }
    } else {
        // Full float fallback: classify src from g_aggd inline.
        float w00 = W[0], w01 = W[1], w10 = W[2], w11 = W[3];
        if (g_idx64 == 0) {
            const int* src = (const int*)eiv;
            const int* dst = src + E;
            for (long long q = tid; q < quads; q += stride) {
                int4 s = __ldcs((const int4*)(src + 4 * q));
                int4 d = __ldcs((const int4*)(dst + 4 * q));
                #pragma unroll
                for (int j = 0; j < 4; j++) {
                    int sn = (&s.x)[j], dn = (&d.x)[j];
                    float4 ad = ldcg_f4(&g_aggd[sn]);
                    float x0, x1;
                    classify(ad.x, ad.y, w00, w01, w10, w11, x0, x1);
                    red_add_f32x2(&g_agg[dn], x0, x1);
                }
            }
            if (tid == 0) {
                for (long long e = quads * 4; e < E; e++) {
                    float4 ad = ldcg_f4(&g_aggd[src[e]]);
                    float x0, x1;
                    classify(ad.x, ad.y, w00, w01, w10, w11, x0, x1);
                    red_add_f32x2(&g_agg[dst[e]], x0, x1);
                }
            }
        } else {
            const long long* src = (const long long*)eiv;
            const long long* dst = src + E;
            for (long long q = tid; q < quads; q += stride) {
                #pragma unroll
                for (int j = 0; j < 4; j++) {
                    int sn = (int)src[4 * q + j], dn = (int)dst[4 * q + j];
                    float4 ad = ldcg_f4(&g_aggd[sn]);
                    float x0, x1;
                    classify(ad.x, ad.y, w00, w01, w10, w11, x0, x1);
                    red_add_f32x2(&g_agg[dn], x0, x1);
                }
            }
            if (tid == 0) {
                for (long long e = quads * 4; e < E; e++) {
                    float4 ad = ldcg_f4(&g_aggd[(int)src[e]]);
                    float x0, x1;
                    classify(ad.x, ad.y, w00, w01, w10, w11, x0, x1);
                    red_add_f32x2(&g_agg[(int)dst[e]], x0, x1);
                }
            }
        }
    }
}

// ---------------------------------------------------------------------------
// Kernel 4: final. Three tiers:
//   all-class-1 (expected): agg = (0, deg)            (reads only g_aggd)
//   clean w/ rare classes:  unpack w: c2 = floor(w/65536), cA = w - 65536*c2
//                           agg = (cA, deg - cA - c2)
//   class-3 present:        float g_agg fallback
// ---------------------------------------------------------------------------
__global__ void k_final(const float* __restrict__ W,
                        const float* __restrict__ fw,
                        float2* __restrict__ out, int Npairs) {
    int i = blockIdx.x * blockDim.x + threadIdx.x;
    float w00 = W[0], w01 = W[1], w10 = W[2], w11 = W[3];
    float f0 = fw[0], f1 = fw[1];
    PDL_WAIT();
    if (i >= Npairs) return;

    float4 a;
    if (g_notclean == 0) {
        float4 ad0 = g_aggd[2 * i];
        float4 ad1 = g_aggd[2 * i + 1];
        if (g_anyAB == 0) {
            a = make_float4(0.0f, ad0.z, 0.0f, ad1.z);
        } else {
            float c2_0 = floorf(ad0.w / C2_SCALE);
            float cA_0 = ad0.w - c2_0 * C2_SCALE;
            float c2_1 = floorf(ad1.w / C2_SCALE);
            float cA_1 = ad1.w - c2_1 * C2_SCALE;
            a = make_float4(cA_0, ad0.z - cA_0 - c2_0,
                            cA_1, ad1.z - cA_1 - c2_1);
        }
    } else {
        a = ((const float4*)g_agg)[i];
    }
    float y0 = fmaxf(fmaf(a.y, w10, a.x * w00), 0.0f);
    float y1 = fmaxf(fmaf(a.y, w11, a.x * w01), 0.0f);
    float y2 = fmaxf(fmaf(a.w, w10, a.z * w00), 0.0f);
    float y3 = fmaxf(fmaf(a.w, w11, a.z * w01), 0.0f);
    float s0 = fmaf(y1, f1, y0 * f0);
    float s1 = fmaf(y3, f1, y2 * f0);
    out[i] = make_float2(1.0f / (1.0f + expf(-s0)),
                         1.0f / (1.0f + expf(-s1)));
}

// ---------------------------------------------------------------------------
// Launch: init -> scatter(v4+deg) -> mid(classify) -> scatter2(gated) ->
// final, all under PDL. Graph-capturable, allocation-free.
// ---------------------------------------------------------------------------
extern "C" void kernel_launch(void* const* d_in, const int* in_sizes, int n_in,
                              void* d_out, int out_size) {
    const float* x  = (const float*)d_in[0];
    const void*  ei = (const void*)d_in[1];
    const float* W  = (const float*)d_in[2];
    const float* fw = (const float*)d_in[3];
    float2* out = (float2*)d_out;

    int N = in_sizes[0] / 2;          // 1,000,000 (divisible by 4)
    int Npairs = N / 2;
    int Nquads = N / 4;
    long long E = (long long)in_sizes[1] / 2;
    long long equads = E >> 2;

    const int TB = 256;
    int nb_pairs = (Npairs + TB - 1) / TB;
    int nb_quads = (Nquads + TB - 1) / TB;
    int nb_scatter = (int)((equads + TB - 1) / TB);
    const int GATED_BLOCKS = 512;     // small grid: fast exit on expected path

    cudaLaunchAttribute attr[1];
    attr[0].id = cudaLaunchAttributeProgrammaticStreamSerialization;
    attr[0].val.programmaticStreamSerializationAllowed = 1;

    cudaLaunchConfig_t cfg = {};
    cfg.blockDim = dim3(TB, 1, 1);
    cfg.dynamicSmemBytes = 0;
    cfg.stream = 0;
    cfg.attrs = attr;
    cfg.numAttrs = 1;

    cfg.gridDim = dim3(nb_pairs, 1, 1);
    cudaLaunchKernelEx(&cfg, k_init, (const float4*)x, Npairs, N,
                       (const long long*)ei, E);

    cfg.gridDim = dim3(nb_scatter, 1, 1);
    cudaLaunchKernelEx(&cfg, k_scatter, (const void*)ei, E);

    cfg.gridDim = dim3(nb_quads, 1, 1);
    cudaLaunchKernelEx(&cfg, k_mid, W, Nquads);

    cfg.gridDim = dim3(GATED_BLOCKS, 1, 1);
    cudaLaunchKernelEx(&cfg, k_scatter2, (const void*)ei, E, W);

    cfg.gridDim = dim3(nb_pairs, 1, 1);
    cudaLaunchKernelEx(&cfg, k_final, W, fw, out, Npairs);

    (void)n_in; (void)out_size;
}